// round 1
// baseline (speedup 1.0000x reference)
#include <cuda_runtime.h>
#include <math.h>

#define BB   2
#define LL   9216
#define MT   (BB*LL)      // 18432 tokens
#define NCH  72           // chunks per sequence
#define CHL  128          // chunk length: 72*128 = 9216

// ---------------- scratch (static __device__, no allocation) ----------------
__device__ float g_seq[MT*64];          // normalized+clipped, token-major (also the residual)
__device__ float g_xz[MT*256];          // GEMM1 out: x_pre [0:128), z [128:256)
__device__ float g_x[MT*128];           // conv+silu output
__device__ float g_dbc[MT*192];         // fused xproj out: dt_raw[0:128) B[128:144) C[144:160) pad[160:192)
__device__ float g_y[MT*128];           // scan output (gated)
__device__ float g_aggA[BB*128*NCH*16];
__device__ float g_aggB[BB*128*NCH*16];
__device__ float g_h0  [BB*128*NCH*16];
__device__ float g_A[128*16];           // A = -exp(A_log)
__device__ float g_Wcat[192*128];       // rows 0..127: W_dt@W_xproj[:4]; 128..159: B/C rows; 160..191: 0
__device__ float g_bcat[192];           // b_dt then zeros
__device__ float g_Wf[64*128];          // bnscale * proj_w @ W_out
__device__ float g_bf[64];
__device__ float g_part[BB*64*2];
__device__ float g_stats[2*BB];         // mu, rstd per batch

__device__ __forceinline__ float softplus_f(float v) {
    return (v > 15.f) ? v : log1pf(__expf(v));
}

// ---------------- setup: A, fused weights ----------------
__global__ void k_setup(const float* __restrict__ A_log, const float* __restrict__ W_xproj,
                        const float* __restrict__ W_dt, const float* __restrict__ b_dt,
                        const float* __restrict__ proj_w, const float* __restrict__ W_out,
                        const float* __restrict__ b_out, const float* __restrict__ proj_b,
                        const float* __restrict__ bn_g, const float* __restrict__ bn_b,
                        const float* __restrict__ bn_m, const float* __restrict__ bn_v) {
    int tid = blockIdx.x*blockDim.x + threadIdx.x;
    int nth = gridDim.x*blockDim.x;
    const int NA = 2048, NW = 24576, NB = 192, NF = 8192, NBF = 64;
    for (int i = tid; i < NA+NW+NB+NF+NBF; i += nth) {
        if (i < NA) {
            g_A[i] = -expf(A_log[i]);
        } else if (i < NA+NW) {
            int j = i - NA; int row = j >> 7; int k = j & 127;
            float v = 0.f;
            if (row < 128) {
                #pragma unroll
                for (int r = 0; r < 4; r++) v = fmaf(W_dt[row*4+r], W_xproj[r*128+k], v);
            } else if (row < 160) {
                v = W_xproj[(row-124)*128 + k];
            }
            g_Wcat[j] = v;
        } else if (i < NA+NW+NB) {
            int j = i - (NA+NW);
            g_bcat[j] = (j < 128) ? b_dt[j] : 0.f;
        } else if (i < NA+NW+NB+NF) {
            int j = i - (NA+NW+NB); int c = j >> 7; int d = j & 127;
            float sc = bn_g[c]*rsqrtf(bn_v[c]+1e-5f);
            float acc = 0.f;
            for (int o = 0; o < 64; o++) acc = fmaf(proj_w[c*64+o], W_out[o*128+d], acc);
            g_Wf[j] = sc*acc;
        } else {
            int c = i - (NA+NW+NB+NF);
            float sc = bn_g[c]*rsqrtf(bn_v[c]+1e-5f);
            float acc = proj_b[c];
            for (int o = 0; o < 64; o++) acc = fmaf(proj_w[c*64+o], b_out[o], acc);
            g_bf[c] = sc*(acc - bn_m[c]) + bn_b[c];
        }
    }
}

// ---------------- per-batch mean/var (two stage, deterministic) ----------------
__global__ void k_red1(const float* __restrict__ x) {
    __shared__ float s1[256], s2[256];
    int b = blockIdx.y;
    const float* p = x + b*589824 + blockIdx.x*9216;
    float s = 0.f, q = 0.f;
    for (int i = threadIdx.x; i < 9216; i += 256) { float v = p[i]; s += v; q = fmaf(v, v, q); }
    s1[threadIdx.x] = s; s2[threadIdx.x] = q;
    __syncthreads();
    for (int st = 128; st > 0; st >>= 1) {
        if (threadIdx.x < st) { s1[threadIdx.x] += s1[threadIdx.x+st]; s2[threadIdx.x] += s2[threadIdx.x+st]; }
        __syncthreads();
    }
    if (threadIdx.x == 0) {
        g_part[(b*64+blockIdx.x)*2+0] = s1[0];
        g_part[(b*64+blockIdx.x)*2+1] = s2[0];
    }
}

__global__ void k_red2() {
    __shared__ float s1[64], s2[64];
    int b = blockIdx.x;
    s1[threadIdx.x] = g_part[(b*64+threadIdx.x)*2+0];
    s2[threadIdx.x] = g_part[(b*64+threadIdx.x)*2+1];
    __syncthreads();
    for (int st = 32; st > 0; st >>= 1) {
        if (threadIdx.x < st) { s1[threadIdx.x] += s1[threadIdx.x+st]; s2[threadIdx.x] += s2[threadIdx.x+st]; }
        __syncthreads();
    }
    if (threadIdx.x == 0) {
        float n = 589824.f;
        float mu = s1[0]/n;
        float var = fmaxf(s2[0]/n - mu*mu, 0.f);
        g_stats[b*2+0] = mu;
        g_stats[b*2+1] = rsqrtf(var + 1e-5f);
    }
}

// ---------------- norm + clip + transpose NCHW -> token-major ----------------
__global__ void k_norm_t(const float* __restrict__ x, const float* __restrict__ gg,
                         const float* __restrict__ gb) {
    __shared__ float t[64*33];
    int b = blockIdx.y, l0 = blockIdx.x*32;
    float mu = g_stats[b*2+0], rs = g_stats[b*2+1];
    #pragma unroll
    for (int it = 0; it < 8; it++) {
        int idx = it*256 + threadIdx.x;
        int c = idx >> 5, li = idx & 31;
        float v = x[(b*64+c)*LL + l0 + li];
        v = (v - mu)*rs*gg[c] + gb[c];
        v = fminf(fmaxf(v, -10.f), 10.f);
        t[c*33+li] = v;
    }
    __syncthreads();
    #pragma unroll
    for (int it = 0; it < 8; it++) {
        int idx = it*256 + threadIdx.x;
        int lp = idx >> 6, c = idx & 63;
        g_seq[(b*LL + l0 + lp)*64 + c] = t[c*33+lp];
    }
}

// ---------------- generic register-tiled GEMM: C[M,N] = A[M,K] @ W[N,K]^T + bias ----------------
template<int K>
__global__ __launch_bounds__(256) void k_gemm(const float* __restrict__ A,
                                              const float* __restrict__ W,
                                              const float* __restrict__ bias,
                                              float* __restrict__ C, int N) {
    extern __shared__ float sm[];
    float* As = sm;            // K x 68 (m inner)
    float* Ws = sm + K*68;     // K x 68 (n inner)
    int m0 = blockIdx.x*64, n0 = blockIdx.y*64;
    for (int idx = threadIdx.x; idx < 64*K; idx += 256) {
        int m = idx / K, k = idx % K;
        As[k*68+m] = A[(m0+m)*K + k];
    }
    for (int idx = threadIdx.x; idx < 64*K; idx += 256) {
        int n = idx / K, k = idx % K;
        Ws[k*68+n] = W[(n0+n)*K + k];
    }
    __syncthreads();
    int tx = threadIdx.x & 15, ty = threadIdx.x >> 4;
    float acc[4][4] = {};
    #pragma unroll 8
    for (int k = 0; k < K; k++) {
        float4 a = *(const float4*)(As + k*68 + tx*4);
        float4 w = *(const float4*)(Ws + k*68 + ty*4);
        float av[4] = {a.x, a.y, a.z, a.w};
        float wv[4] = {w.x, w.y, w.z, w.w};
        #pragma unroll
        for (int i = 0; i < 4; i++)
            #pragma unroll
            for (int j = 0; j < 4; j++)
                acc[i][j] = fmaf(av[i], wv[j], acc[i][j]);
    }
    float4 bv = *(const float4*)(bias + n0 + ty*4);
    #pragma unroll
    for (int i = 0; i < 4; i++) {
        float4 o;
        o.x = acc[i][0]+bv.x; o.y = acc[i][1]+bv.y;
        o.z = acc[i][2]+bv.z; o.w = acc[i][3]+bv.w;
        *(float4*)(C + (size_t)(m0+tx*4+i)*N + n0 + ty*4) = o;
    }
}

// ---------------- depthwise causal conv (width 4) + bias + silu ----------------
__global__ void k_conv(const float* __restrict__ cw, const float* __restrict__ cb) {
    __shared__ float t[19*128];
    int b = blockIdx.y, l0 = blockIdx.x*16;
    for (int idx = threadIdx.x; idx < 19*128; idx += 256) {
        int r = idx >> 7, d = idx & 127;
        int l = l0 - 3 + r;
        t[idx] = (l >= 0) ? g_xz[(b*LL + l)*256 + d] : 0.f;
    }
    __syncthreads();
    #pragma unroll
    for (int it = 0; it < 8; it++) {
        int idx = it*256 + threadIdx.x;
        int tt = idx >> 7, d = idx & 127;
        float acc = cb[d];
        #pragma unroll
        for (int j = 0; j < 4; j++) acc = fmaf(cw[d*4+j], t[(tt+j)*128 + d], acc);
        float sv = acc / (1.f + __expf(-acc));
        g_x[(b*LL + l0 + tt)*128 + d] = sv;
    }
}

// ---------------- chunked scan: pass 1 (per-chunk aggregates) ----------------
// warp -> (b, d, chunk-pair); lanes 0..15 = states of chunk 2*c2, 16..31 = chunk 2*c2+1
__global__ __launch_bounds__(256) void k_scan1() {
    int w = (blockIdx.x*256 + threadIdx.x) >> 5;
    int lane = threadIdx.x & 31;
    int d  = w & 127;
    int c2 = (w >> 7) % 36;
    int b  = w / (128*36);
    int s = lane & 15;
    int chunk = c2*2 + (lane >> 4);
    float a = g_A[d*16+s];
    int m = b*LL + chunk*CHL;
    float aA = 1.f, aB = 0.f;
    for (int i = 0; i < CHL; i++, m++) {
        float dt = softplus_f(g_dbc[m*192 + d]);
        float xv = g_x[m*128 + d];
        float Bv = g_dbc[m*192 + 128 + s];
        float dA = __expf(dt*a);
        aA *= dA;
        aB = fmaf(dA, aB, dt*Bv*xv);
    }
    int o = ((b*128+d)*NCH + chunk)*16 + s;
    g_aggA[o] = aA; g_aggB[o] = aB;
}

// ---------------- scan pass 2: combine chunk aggregates (exclusive) ----------------
__global__ void k_scan2() {
    int idx = blockIdx.x*256 + threadIdx.x;   // < 4096
    int bd = idx >> 4, s = idx & 15;
    float h = 0.f;
    for (int c = 0; c < NCH; c++) {
        int o = (bd*NCH + c)*16 + s;
        g_h0[o] = h;
        h = fmaf(g_aggA[o], h, g_aggB[o]);
    }
}

// ---------------- scan pass 3: replay + y = (sum_s h*C + x*D) * silu(z) ----------------
__global__ __launch_bounds__(256) void k_scan3(const float* __restrict__ Dp) {
    int w = (blockIdx.x*256 + threadIdx.x) >> 5;
    int lane = threadIdx.x & 31;
    int d  = w & 127;
    int c2 = (w >> 7) % 36;
    int b  = w / (128*36);
    int s = lane & 15;
    int chunk = c2*2 + (lane >> 4);
    float a = g_A[d*16+s];
    float Dpv = Dp[d];
    int o = ((b*128+d)*NCH + chunk)*16 + s;
    float h = g_h0[o];
    int m = b*LL + chunk*CHL;
    for (int i = 0; i < CHL; i++, m++) {
        float dt = softplus_f(g_dbc[m*192 + d]);
        float xv = g_x[m*128 + d];
        float Bv = g_dbc[m*192 + 128 + s];
        float Cv = g_dbc[m*192 + 144 + s];
        float dA = __expf(dt*a);
        h = fmaf(dA, h, dt*Bv*xv);
        float yv = h*Cv;
        yv += __shfl_xor_sync(0xffffffffu, yv, 8);
        yv += __shfl_xor_sync(0xffffffffu, yv, 4);
        yv += __shfl_xor_sync(0xffffffffu, yv, 2);
        yv += __shfl_xor_sync(0xffffffffu, yv, 1);
        if (s == 0) {
            float zv = g_xz[m*256 + 128 + d];
            float silu = zv / (1.f + __expf(-zv));
            g_y[m*128 + d] = (yv + xv*Dpv) * silu;
        }
    }
}

// ---------------- final fused GEMM (64x128) + gelu + residual + clip + transpose ----------------
__global__ __launch_bounds__(256) void k_gemm2(float* __restrict__ out) {
    extern __shared__ float sm[];
    float* As = sm;             // 128 x 68
    float* Ws = sm + 128*68;    // 128 x 68 (only 64 cols used)
    int m0 = blockIdx.x*64;
    for (int idx = threadIdx.x; idx < 64*128; idx += 256) {
        int m = idx >> 7, k = idx & 127;
        As[k*68+m] = g_y[(m0+m)*128 + k];
    }
    for (int idx = threadIdx.x; idx < 64*128; idx += 256) {
        int n = idx >> 7, k = idx & 127;
        Ws[k*68+n] = g_Wf[n*128 + k];
    }
    __syncthreads();
    int tx = threadIdx.x & 15, ty = threadIdx.x >> 4;
    float acc[4][4] = {};
    #pragma unroll 8
    for (int k = 0; k < 128; k++) {
        float4 a = *(const float4*)(As + k*68 + tx*4);
        float4 w = *(const float4*)(Ws + k*68 + ty*4);
        float av[4] = {a.x, a.y, a.z, a.w};
        float wv[4] = {w.x, w.y, w.z, w.w};
        #pragma unroll
        for (int i = 0; i < 4; i++)
            #pragma unroll
            for (int j = 0; j < 4; j++)
                acc[i][j] = fmaf(av[i], wv[j], acc[i][j]);
    }
    __syncthreads();      // done reading As/Ws — reuse smem
    float* Os = sm;       // 64(n) x 68
    #pragma unroll
    for (int i = 0; i < 4; i++) {
        int m = m0 + tx*4 + i;
        #pragma unroll
        for (int j = 0; j < 4; j++) {
            int n = ty*4 + j;
            float o = acc[i][j] + g_bf[n];
            float g = 0.5f*o*(1.f + erff(o*0.70710678118654752f));
            float r = g_seq[m*64 + n];
            float f = fminf(fmaxf(r + g, -10.f), 10.f);
            Os[n*68 + (tx*4+i)] = f;
        }
    }
    __syncthreads();
    int b = m0 / LL, l0 = m0 % LL;
    for (int idx = threadIdx.x; idx < 4096; idx += 256) {
        int c = idx >> 6, tloc = idx & 63;
        out[(b*64+c)*LL + l0 + tloc] = Os[c*68 + tloc];
    }
}

// ---------------- launch ----------------
extern "C" void kernel_launch(void* const* d_in, const int* in_sizes, int n_in,
                              void* d_out, int out_size) {
    const float* x        = (const float*)d_in[0];
    const float* gn_gamma = (const float*)d_in[1];
    const float* gn_beta  = (const float*)d_in[2];
    const float* W_in     = (const float*)d_in[3];
    const float* b_in     = (const float*)d_in[4];
    const float* conv_w   = (const float*)d_in[5];
    const float* conv_b   = (const float*)d_in[6];
    const float* W_xproj  = (const float*)d_in[7];
    const float* W_dt     = (const float*)d_in[8];
    const float* b_dt     = (const float*)d_in[9];
    const float* A_log    = (const float*)d_in[10];
    const float* Dp       = (const float*)d_in[11];
    const float* W_out    = (const float*)d_in[12];
    const float* b_out    = (const float*)d_in[13];
    const float* proj_w   = (const float*)d_in[14];
    const float* proj_b   = (const float*)d_in[15];
    const float* bn_gamma = (const float*)d_in[16];
    const float* bn_beta  = (const float*)d_in[17];
    const float* bn_mean  = (const float*)d_in[18];
    const float* bn_var   = (const float*)d_in[19];
    float* out = (float*)d_out;

    // opt-in for >48KB dynamic smem (idempotent, host-side only)
    cudaFuncSetAttribute((const void*)k_gemm<128>, cudaFuncAttributeMaxDynamicSharedMemorySize, 128*68*2*4);
    cudaFuncSetAttribute((const void*)k_gemm2,     cudaFuncAttributeMaxDynamicSharedMemorySize, 128*68*2*4);

    float *p_seq, *p_xz, *p_x, *p_dbc, *p_Wcat, *p_bcat;
    cudaGetSymbolAddress((void**)&p_seq,  g_seq);
    cudaGetSymbolAddress((void**)&p_xz,   g_xz);
    cudaGetSymbolAddress((void**)&p_x,    g_x);
    cudaGetSymbolAddress((void**)&p_dbc,  g_dbc);
    cudaGetSymbolAddress((void**)&p_Wcat, g_Wcat);
    cudaGetSymbolAddress((void**)&p_bcat, g_bcat);

    k_setup<<<32, 256>>>(A_log, W_xproj, W_dt, b_dt, proj_w, W_out, b_out, proj_b,
                         bn_gamma, bn_beta, bn_mean, bn_var);
    k_red1<<<dim3(64,2), 256>>>(x);
    k_red2<<<2, 64>>>();
    k_norm_t<<<dim3(288,2), 256>>>(x, gn_gamma, gn_beta);
    // GEMM1: xz = seq @ W_in^T + b_in   (K=64, N=256)
    k_gemm<64><<<dim3(288,4), 256, 64*68*2*4>>>(p_seq, W_in, b_in, p_xz, 256);
    k_conv<<<dim3(576,2), 256>>>(conv_w, conv_b);
    // fused xproj+dt GEMM: dbc = x @ Wcat^T + bcat   (K=128, N=192)
    k_gemm<128><<<dim3(288,3), 256, 128*68*2*4>>>(p_x, p_Wcat, p_bcat, p_dbc, 192);
    k_scan1<<<1152, 256>>>();
    k_scan2<<<16, 256>>>();
    k_scan3<<<1152, 256>>>(Dp);
    k_gemm2<<<288, 256, 128*68*2*4>>>(out);
}

// round 2
// speedup vs baseline: 1.6564x; 1.6564x over previous
#include <cuda_runtime.h>
#include <math.h>

#define BB   2
#define LL   9216
#define MT   (BB*LL)
#define NCH  72
#define CHL  128

// ---------------- scratch ----------------
__device__ float g_xpre[MT*128];   // pre-conv x
__device__ float g_zs[MT*128];     // silu(z)
__device__ float g_x[MT*128];      // conv+silu output
__device__ float g_dt2[MT*256];    // interleaved (softplus(dt), dt*x) per (m,d)
__device__ float g_bc[MT*32];      // interleaved (B_s, C_s)
__device__ float g_xd[MT*128];     // x*Dp
__device__ float g_y[MT*128];      // scan output (gated)
__device__ float g_aggA[BB*128*NCH*16];
__device__ float g_aggB[BB*128*NCH*16];
__device__ float g_h0  [BB*128*NCH*16];
__device__ float g_A2[128*16];     // -exp(A_log) * log2(e)
__device__ float g_Wcat[192*128];
__device__ float g_bcat[192];
__device__ float g_Wf[64*128];
__device__ float g_bf[64];
__device__ float g_part[BB*64*2];
__device__ float g_stats[2*BB];

__device__ __forceinline__ float ex2f(float x) {
    float y; asm("ex2.approx.f32 %0, %1;" : "=f"(y) : "f"(x)); return y;
}
__device__ __forceinline__ float softplus_f(float v) {
    return (v > 15.f) ? v : log1pf(__expf(v));
}
__device__ __forceinline__ float siluf(float v) {
    return v / (1.f + __expf(-v));
}

// ---------------- setup ----------------
__global__ void k_setup(const float* __restrict__ A_log, const float* __restrict__ W_xproj,
                        const float* __restrict__ W_dt, const float* __restrict__ b_dt,
                        const float* __restrict__ proj_w, const float* __restrict__ W_out,
                        const float* __restrict__ b_out, const float* __restrict__ proj_b,
                        const float* __restrict__ bn_g, const float* __restrict__ bn_b,
                        const float* __restrict__ bn_m, const float* __restrict__ bn_v) {
    int tid = blockIdx.x*blockDim.x + threadIdx.x;
    int nth = gridDim.x*blockDim.x;
    const int NA = 2048, NW = 24576, NB = 192, NF = 8192, NBF = 64;
    for (int i = tid; i < NA+NW+NB+NF+NBF; i += nth) {
        if (i < NA) {
            g_A2[i] = -expf(A_log[i]) * 1.4426950408889634f;
        } else if (i < NA+NW) {
            int j = i - NA; int row = j >> 7; int k = j & 127;
            float v = 0.f;
            if (row < 128) {
                #pragma unroll
                for (int r = 0; r < 4; r++) v = fmaf(W_dt[row*4+r], W_xproj[r*128+k], v);
            } else if (row < 160) {
                v = W_xproj[(row-124)*128 + k];
            }
            g_Wcat[j] = v;
        } else if (i < NA+NW+NB) {
            int j = i - (NA+NW);
            g_bcat[j] = (j < 128) ? b_dt[j] : 0.f;
        } else if (i < NA+NW+NB+NF) {
            int j = i - (NA+NW+NB); int c = j >> 7; int d = j & 127;
            float sc = bn_g[c]*rsqrtf(bn_v[c]+1e-5f);
            float acc = 0.f;
            for (int o = 0; o < 64; o++) acc = fmaf(proj_w[c*64+o], W_out[o*128+d], acc);
            g_Wf[j] = sc*acc;
        } else {
            int c = i - (NA+NW+NB+NF);
            float sc = bn_g[c]*rsqrtf(bn_v[c]+1e-5f);
            float acc = proj_b[c];
            for (int o = 0; o < 64; o++) acc = fmaf(proj_w[c*64+o], b_out[o], acc);
            g_bf[c] = sc*(acc - bn_m[c]) + bn_b[c];
        }
    }
}

// ---------------- per-batch mean/var ----------------
__global__ void k_red1(const float* __restrict__ x) {
    __shared__ float s1[256], s2[256];
    int b = blockIdx.y;
    const float* p = x + b*589824 + blockIdx.x*9216;
    float s = 0.f, q = 0.f;
    for (int i = threadIdx.x; i < 9216; i += 256) { float v = p[i]; s += v; q = fmaf(v, v, q); }
    s1[threadIdx.x] = s; s2[threadIdx.x] = q;
    __syncthreads();
    for (int st = 128; st > 0; st >>= 1) {
        if (threadIdx.x < st) { s1[threadIdx.x] += s1[threadIdx.x+st]; s2[threadIdx.x] += s2[threadIdx.x+st]; }
        __syncthreads();
    }
    if (threadIdx.x == 0) {
        g_part[(b*64+blockIdx.x)*2+0] = s1[0];
        g_part[(b*64+blockIdx.x)*2+1] = s2[0];
    }
}

__global__ void k_red2() {
    __shared__ float s1[64], s2[64];
    int b = blockIdx.x;
    s1[threadIdx.x] = g_part[(b*64+threadIdx.x)*2+0];
    s2[threadIdx.x] = g_part[(b*64+threadIdx.x)*2+1];
    __syncthreads();
    for (int st = 32; st > 0; st >>= 1) {
        if (threadIdx.x < st) { s1[threadIdx.x] += s1[threadIdx.x+st]; s2[threadIdx.x] += s2[threadIdx.x+st]; }
        __syncthreads();
    }
    if (threadIdx.x == 0) {
        float n = 589824.f;
        float mu = s1[0]/n;
        float var = fmaxf(s2[0]/n - mu*mu, 0.f);
        g_stats[b*2+0] = mu;
        g_stats[b*2+1] = rsqrtf(var + 1e-5f);
    }
}

// ---------------- GEMM1: normalized x (inline) @ W_in^T; writes g_xpre + silu(z) ----------------
// tile 128m x 256n, 256 threads, microtile 8x16, K=64. grid 144 (one wave).
__global__ __launch_bounds__(256, 1) void k_gemm1(const float* __restrict__ x,
                                                  const float* __restrict__ gg,
                                                  const float* __restrict__ gb,
                                                  const float* __restrict__ W_in,
                                                  const float* __restrict__ b_in) {
    extern __shared__ float sm[];
    float* As = sm;             // [k=64][m=128] stride 136
    float* Ws = sm + 64*136;    // [k=64][n=256] stride 264
    int blk = blockIdx.x;
    int b = blk / 72;
    int l0 = (blk % 72) * 128;
    float mu = g_stats[b*2+0], rs = g_stats[b*2+1];
    for (int idx = threadIdx.x; idx < 64*128; idx += 256) {
        int c = idx >> 7, li = idx & 127;
        float v = x[(b*64+c)*LL + l0 + li];
        v = (v - mu)*rs*gg[c] + gb[c];
        v = fminf(fmaxf(v, -10.f), 10.f);
        As[c*136 + li] = v;
    }
    for (int idx = threadIdx.x; idx < 256*64; idx += 256) {
        int n = idx >> 6, k = idx & 63;
        Ws[k*264 + n] = W_in[idx];
    }
    __syncthreads();
    int tx = threadIdx.x & 15, ty = threadIdx.x >> 4;
    float acc[8][16];
    #pragma unroll
    for (int i = 0; i < 8; i++)
        #pragma unroll
        for (int j = 0; j < 16; j++) acc[i][j] = 0.f;
    #pragma unroll 4
    for (int k = 0; k < 64; k++) {
        float4 a0 = *(const float4*)(As + k*136 + tx*8);
        float4 a1 = *(const float4*)(As + k*136 + tx*8 + 4);
        float4 w0 = *(const float4*)(Ws + k*264 + ty*16);
        float4 w1 = *(const float4*)(Ws + k*264 + ty*16 + 4);
        float4 w2 = *(const float4*)(Ws + k*264 + ty*16 + 8);
        float4 w3 = *(const float4*)(Ws + k*264 + ty*16 + 12);
        float av[8] = {a0.x,a0.y,a0.z,a0.w,a1.x,a1.y,a1.z,a1.w};
        float wv[16] = {w0.x,w0.y,w0.z,w0.w,w1.x,w1.y,w1.z,w1.w,
                        w2.x,w2.y,w2.z,w2.w,w3.x,w3.y,w3.z,w3.w};
        #pragma unroll
        for (int i = 0; i < 8; i++)
            #pragma unroll
            for (int j = 0; j < 16; j++)
                acc[i][j] = fmaf(av[i], wv[j], acc[i][j]);
    }
    float bv[16];
    #pragma unroll
    for (int j = 0; j < 16; j++) bv[j] = b_in[ty*16 + j];
    int mt0 = b*LL + l0 + tx*8;
    bool zhalf = (ty >= 8);
    #pragma unroll
    for (int i = 0; i < 8; i++) {
        int mt = mt0 + i;
        #pragma unroll
        for (int jj = 0; jj < 16; jj += 4) {
            float4 o;
            o.x = acc[i][jj+0] + bv[jj+0];
            o.y = acc[i][jj+1] + bv[jj+1];
            o.z = acc[i][jj+2] + bv[jj+2];
            o.w = acc[i][jj+3] + bv[jj+3];
            if (!zhalf) {
                *(float4*)(g_xpre + (size_t)mt*128 + ty*16 + jj) = o;
            } else {
                o.x = siluf(o.x); o.y = siluf(o.y); o.z = siluf(o.z); o.w = siluf(o.w);
                *(float4*)(g_zs + (size_t)mt*128 + (ty-8)*16 + jj) = o;
            }
        }
    }
}

// ---------------- depthwise causal conv (w=4) + bias + silu ----------------
__global__ void k_conv(const float* __restrict__ cw, const float* __restrict__ cb) {
    __shared__ float t[19*128];
    int b = blockIdx.y, l0 = blockIdx.x*16;
    for (int idx = threadIdx.x; idx < 19*128; idx += 256) {
        int r = idx >> 7, d = idx & 127;
        int l = l0 - 3 + r;
        t[idx] = (l >= 0) ? g_xpre[(b*LL + l)*128 + d] : 0.f;
    }
    __syncthreads();
    #pragma unroll
    for (int it = 0; it < 8; it++) {
        int idx = it*256 + threadIdx.x;
        int tt = idx >> 7, d = idx & 127;
        float acc = cb[d];
        #pragma unroll
        for (int j = 0; j < 4; j++) acc = fmaf(cw[d*4+j], t[(tt+j)*128 + d], acc);
        g_x[(b*LL + l0 + tt)*128 + d] = siluf(acc);
    }
}

// ---------------- xproj GEMM: g_x @ Wcat^T; epilogue fuses softplus, dt*x, x*Dp, B/C pack ----------------
// tile 128m x 192n, 256 threads, microtile 8x12, K=128. grid 144.
__global__ __launch_bounds__(256, 1) void k_gemmX(const float* __restrict__ Dp) {
    extern __shared__ float sm[];
    float* As = sm;              // [k=128][m=128] stride 136
    float* Ws = sm + 128*136;    // [k=128][n=192] stride 200
    int blk = blockIdx.x;
    int b = blk / 72;
    int l0 = (blk % 72) * 128;
    int m0 = b*LL + l0;
    for (int idx = threadIdx.x; idx < 128*128; idx += 256) {
        int m = idx >> 7, k = idx & 127;
        As[k*136 + m] = g_x[(size_t)(m0+m)*128 + k];
    }
    for (int idx = threadIdx.x; idx < 192*128; idx += 256) {
        int n = idx >> 7, k = idx & 127;
        Ws[k*200 + n] = g_Wcat[idx];
    }
    __syncthreads();
    int tx = threadIdx.x & 15, ty = threadIdx.x >> 4;
    float acc[8][12];
    #pragma unroll
    for (int i = 0; i < 8; i++)
        #pragma unroll
        for (int j = 0; j < 12; j++) acc[i][j] = 0.f;
    #pragma unroll 2
    for (int k = 0; k < 128; k++) {
        float4 a0 = *(const float4*)(As + k*136 + tx*8);
        float4 a1 = *(const float4*)(As + k*136 + tx*8 + 4);
        float4 w0 = *(const float4*)(Ws + k*200 + ty*12);
        float4 w1 = *(const float4*)(Ws + k*200 + ty*12 + 4);
        float4 w2 = *(const float4*)(Ws + k*200 + ty*12 + 8);
        float av[8] = {a0.x,a0.y,a0.z,a0.w,a1.x,a1.y,a1.z,a1.w};
        float wv[12] = {w0.x,w0.y,w0.z,w0.w,w1.x,w1.y,w1.z,w1.w,w2.x,w2.y,w2.z,w2.w};
        #pragma unroll
        for (int i = 0; i < 8; i++)
            #pragma unroll
            for (int j = 0; j < 12; j++)
                acc[i][j] = fmaf(av[i], wv[j], acc[i][j]);
    }
    #pragma unroll
    for (int i = 0; i < 8; i++) {
        int mloc = tx*8 + i;
        int mt = m0 + mloc;
        #pragma unroll
        for (int j = 0; j < 12; j++) {
            int n = ty*12 + j;
            float v = acc[i][j] + g_bcat[n];
            if (n < 128) {
                float dtsp = softplus_f(v);
                float xval = As[n*136 + mloc];
                float2 st; st.x = dtsp; st.y = dtsp*xval;
                *(float2*)(g_dt2 + (size_t)mt*256 + 2*n) = st;
                g_xd[(size_t)mt*128 + n] = xval * Dp[n];
            } else if (n < 144) {
                g_bc[(size_t)mt*32 + 2*(n-128)] = v;
            } else if (n < 160) {
                g_bc[(size_t)mt*32 + 2*(n-144)+1] = v;
            }
        }
    }
}

// ---------------- scan pass 1: per-chunk aggregates ----------------
__global__ __launch_bounds__(256) void k_scan1() {
    int wib = threadIdx.x >> 5;
    int lane = threadIdx.x & 31;
    int blk = blockIdx.x;                // 1152 blocks
    int b = blk / 576;
    int r = blk % 576;
    int c2 = r >> 4;
    int d = ((r & 15) << 3) + wib;
    int s = lane & 15;
    int chunk = c2*2 + (lane >> 4);
    float a2 = g_A2[d*16 + s];
    int m = b*LL + chunk*CHL;
    const float2* pd = (const float2*)g_dt2 + (size_t)m*128 + d;
    const float2* pb = (const float2*)g_bc  + (size_t)m*16  + s;
    float aA = 1.f, aB = 0.f;
    #pragma unroll 4
    for (int i = 0; i < CHL; i++) {
        float2 dd = *pd; pd += 128;
        float2 bc = *pb; pb += 16;
        float dA = ex2f(dd.x * a2);
        aA *= dA;
        aB = fmaf(dA, aB, dd.y * bc.x);
    }
    int o = ((b*128 + d)*NCH + chunk)*16 + s;
    g_aggA[o] = aA; g_aggB[o] = aB;
}

// ---------------- scan pass 2: exclusive combine over chunks ----------------
__global__ void k_scan2() {
    int idx = blockIdx.x*32 + threadIdx.x;   // 4096 total
    int bd = idx >> 4, s = idx & 15;
    float h = 0.f;
    int o = bd*NCH*16 + s;
    #pragma unroll 8
    for (int c = 0; c < NCH; c++) {
        g_h0[o] = h;
        h = fmaf(g_aggA[o], h, g_aggB[o]);
        o += 16;
    }
}

// ---------------- scan pass 3: replay + y = (sum_s h*C + x*D)*silu(z) ----------------
__global__ __launch_bounds__(256) void k_scan3() {
    int wib = threadIdx.x >> 5;
    int lane = threadIdx.x & 31;
    int blk = blockIdx.x;
    int b = blk / 576;
    int r = blk % 576;
    int c2 = r >> 4;
    int d = ((r & 15) << 3) + wib;
    int s = lane & 15;
    int chunk = c2*2 + (lane >> 4);
    float a2 = g_A2[d*16 + s];
    int o = ((b*128 + d)*NCH + chunk)*16 + s;
    float h = g_h0[o];
    int m = b*LL + chunk*CHL;
    const float2* pd = (const float2*)g_dt2 + (size_t)m*128 + d;
    const float2* pb = (const float2*)g_bc  + (size_t)m*16  + s;
    const float* pxd = g_xd + (size_t)m*128 + d;
    const float* pzs = g_zs + (size_t)m*128 + d;
    float* py = g_y + (size_t)m*128 + d;
    bool lead = (s == 0);
    #pragma unroll 2
    for (int i = 0; i < CHL; i++) {
        float2 dd = *pd; pd += 128;
        float2 bc = *pb; pb += 16;
        float dA = ex2f(dd.x * a2);
        h = fmaf(dA, h, dd.y * bc.x);
        float yv = h * bc.y;
        yv += __shfl_xor_sync(0xffffffffu, yv, 8);
        yv += __shfl_xor_sync(0xffffffffu, yv, 4);
        yv += __shfl_xor_sync(0xffffffffu, yv, 2);
        yv += __shfl_xor_sync(0xffffffffu, yv, 1);
        if (lead) {
            float xd = *pxd;
            float zs = *pzs;
            *py = (yv + xd) * zs;
        }
        pxd += 128; pzs += 128; py += 128;
    }
}

// ---------------- final GEMM + gelu + residual(recomputed) + clip + transpose ----------------
// tile 128m x 64n, 128 threads, microtile 8x8, K=128. grid 144.
__global__ __launch_bounds__(128, 1) void k_gemm2f(const float* __restrict__ x,
                                                   const float* __restrict__ gg,
                                                   const float* __restrict__ gb,
                                                   float* __restrict__ out) {
    extern __shared__ float sm[];
    float* As = sm;              // [k=128][m=128] stride 136
    float* Ws = sm + 128*136;    // [k=128][n=64] stride 72
    int blk = blockIdx.x;
    int b = blk / 72;
    int l0 = (blk % 72) * 128;
    int m0 = b*LL + l0;
    for (int idx = threadIdx.x; idx < 128*128; idx += 128) {
        int m = idx >> 7, k = idx & 127;
        As[k*136 + m] = g_y[(size_t)(m0+m)*128 + k];
    }
    for (int idx = threadIdx.x; idx < 64*128; idx += 128) {
        int n = idx >> 7, k = idx & 127;
        Ws[k*72 + n] = g_Wf[idx];
    }
    __syncthreads();
    int tx = threadIdx.x & 15, ty = threadIdx.x >> 4;   // ty in [0,8)
    float acc[8][8];
    #pragma unroll
    for (int i = 0; i < 8; i++)
        #pragma unroll
        for (int j = 0; j < 8; j++) acc[i][j] = 0.f;
    #pragma unroll 2
    for (int k = 0; k < 128; k++) {
        float4 a0 = *(const float4*)(As + k*136 + tx*8);
        float4 a1 = *(const float4*)(As + k*136 + tx*8 + 4);
        float4 w0 = *(const float4*)(Ws + k*72 + ty*8);
        float4 w1 = *(const float4*)(Ws + k*72 + ty*8 + 4);
        float av[8] = {a0.x,a0.y,a0.z,a0.w,a1.x,a1.y,a1.z,a1.w};
        float wv[8] = {w0.x,w0.y,w0.z,w0.w,w1.x,w1.y,w1.z,w1.w};
        #pragma unroll
        for (int i = 0; i < 8; i++)
            #pragma unroll
            for (int j = 0; j < 8; j++)
                acc[i][j] = fmaf(av[i], wv[j], acc[i][j]);
    }
    __syncthreads();
    float* Os = sm;              // reuse: [n=64][m=128] stride 136
    #pragma unroll
    for (int i = 0; i < 8; i++) {
        int mloc = tx*8 + i;
        #pragma unroll
        for (int j = 0; j < 8; j++) {
            int n = ty*8 + j;
            float o = acc[i][j] + g_bf[n];
            float g = 0.5f*o*(1.f + erff(o*0.70710678118654752f));
            Os[n*136 + mloc] = g;
        }
    }
    __syncthreads();
    float mu = g_stats[b*2+0], rs = g_stats[b*2+1];
    for (int idx = threadIdx.x; idx < 64*128; idx += 128) {
        int c = idx >> 7, t = idx & 127;
        float gv = Os[c*136 + t];
        float xv = x[(b*64+c)*LL + l0 + t];
        float res = (xv - mu)*rs*gg[c] + gb[c];
        res = fminf(fmaxf(res, -10.f), 10.f);
        out[(b*64+c)*LL + l0 + t] = fminf(fmaxf(res + gv, -10.f), 10.f);
    }
}

// ---------------- launch ----------------
extern "C" void kernel_launch(void* const* d_in, const int* in_sizes, int n_in,
                              void* d_out, int out_size) {
    const float* x        = (const float*)d_in[0];
    const float* gn_gamma = (const float*)d_in[1];
    const float* gn_beta  = (const float*)d_in[2];
    const float* W_in     = (const float*)d_in[3];
    const float* b_in     = (const float*)d_in[4];
    const float* conv_w   = (const float*)d_in[5];
    const float* conv_b   = (const float*)d_in[6];
    const float* W_xproj  = (const float*)d_in[7];
    const float* W_dt     = (const float*)d_in[8];
    const float* b_dt     = (const float*)d_in[9];
    const float* A_log    = (const float*)d_in[10];
    const float* Dp       = (const float*)d_in[11];
    const float* W_out    = (const float*)d_in[12];
    const float* b_out    = (const float*)d_in[13];
    const float* proj_w   = (const float*)d_in[14];
    const float* proj_b   = (const float*)d_in[15];
    const float* bn_gamma = (const float*)d_in[16];
    const float* bn_beta  = (const float*)d_in[17];
    const float* bn_mean  = (const float*)d_in[18];
    const float* bn_var   = (const float*)d_in[19];
    float* out = (float*)d_out;

    const int SM1 = (64*136 + 64*264) * 4;      // 102400
    const int SMX = (128*136 + 128*200) * 4;    // 172032
    const int SM2 = (128*136 + 128*72) * 4;     // 106496
    cudaFuncSetAttribute((const void*)k_gemm1,  cudaFuncAttributeMaxDynamicSharedMemorySize, SM1);
    cudaFuncSetAttribute((const void*)k_gemmX,  cudaFuncAttributeMaxDynamicSharedMemorySize, SMX);
    cudaFuncSetAttribute((const void*)k_gemm2f, cudaFuncAttributeMaxDynamicSharedMemorySize, SM2);

    k_setup<<<32, 256>>>(A_log, W_xproj, W_dt, b_dt, proj_w, W_out, b_out, proj_b,
                         bn_gamma, bn_beta, bn_mean, bn_var);
    k_red1<<<dim3(64,2), 256>>>(x);
    k_red2<<<2, 64>>>();
    k_gemm1<<<144, 256, SM1>>>(x, gn_gamma, gn_beta, W_in, b_in);
    k_conv<<<dim3(576,2), 256>>>(conv_w, conv_b);
    k_gemmX<<<144, 256, SMX>>>(Dp);
    k_scan1<<<1152, 256>>>();
    k_scan2<<<128, 32>>>();
    k_scan3<<<1152, 256>>>();
    k_gemm2f<<<144, 128, SM2>>>(x, gn_gamma, gn_beta, out);
}